// round 7
// baseline (speedup 1.0000x reference)
#include <cuda_runtime.h>

// BinsChamferLoss: n=16, d=128, h=192, w=256.  Single fused kernel.
// out[b] = (loss1[b] + loss2[b]) / sum(valid_mask)   (count over ALL batches)
//   g = valid ? max(t, bins[b][0]) : bins[b][0]
//   loss1[b] = sum_pixels min_bins |g - bin|   (uniform-LUT lookup + short scan)
//   loss2[b] = sum_bins  min_pixels |g - bin|  (segment min/max + parallel scans)
//
// R7: invalid pixels (50%) skip ALL work (their contribution is statically 0 +
// one per-block b0 segment update); valid-pixel search is a 1024-cell uniform
// LUT (1 gather) + forward scan (~1.1 gathers) instead of a 5-LDS tree descent.

#define NB   16
#define DB   128
#define HW   49152            // 192*256
#define BPB  24               // blocks per batch
#define PPB  (HW / BPB)       // 2048 pixels per block
#define TH   256
#define NSEG (DB + 1)         // segment s in [1,128]; slot 0 unused
#define LUTN 1024
#define INF_BITS 0x7F800000

// Per-block partials (no init required; fully overwritten every replay).
__device__ float        g_pl1 [NB * BPB];
__device__ unsigned int g_pcnt[NB * BPB];
__device__ int          g_pmax[NB * BPB * NSEG];   // float bits; -1 = empty
__device__ int          g_pmin[NB * BPB * NSEG];   // INF_BITS = empty
// Per-batch results + tickets (reset to 0 by their last user each replay).
__device__ float        g_bsum[NB];
__device__ unsigned int g_bcnt[NB];
__device__ unsigned int g_tick_b[NB];
__device__ unsigned int g_tick_g;

__global__ __launch_bounds__(TH) void bcl_fused(const float* __restrict__ bins,
                                                const float* __restrict__ tdm,
                                                const int*   __restrict__ mask,
                                                float*       __restrict__ out) {
    const int batch = blockIdx.x / BPB;
    const int blk   = blockIdx.x % BPB;
    const int bid   = blockIdx.x;
    const int tid   = threadIdx.x;

    __shared__ float sb[NSEG];          // sorted bins + inf pad
    __shared__ int   lut[LUTN];         // lut[q] = upper_bound(edge_q), in [1,128]
    __shared__ int   spmax[NSEG];
    __shared__ int   spmin[NSEG];
    __shared__ int   sflag;             // any invalid pixel seen
    __shared__ float        wl[TH / 32];
    __shared__ unsigned int wc[TH / 32];
    __shared__ unsigned int s_tick;

    if (tid < DB)   sb[tid] = bins[batch * DB + tid];
    if (tid == DB)  sb[DB]  = __int_as_float(INF_BITS);
    for (int i = tid; i < NSEG; i += TH) { spmax[i] = -1; spmin[i] = INF_BITS; }
    if (tid == 0) sflag = 0;
    __syncthreads();

    const float b0  = sb[0];
    const float lutHi    = fmaxf(10.0f, sb[DB - 1]) + 1e-3f;
    const float lutScale = (float)LUTN / (lutHi - b0);
    const float invScale = (lutHi - b0) * (1.0f / (float)LUTN);

    // Build LUT: lut[q] = first s with sb[s] > edge_q, edge_q = b0 + q*invScale.
    // Correctness of the per-pixel scan needs only sb[lut[q]-1] <= edge_q <= g.
    for (int q = tid; q < LUTN; q += TH) {
        const float edge = b0 + (float)q * invScale;
        int lo = 0, hi = DB;
        #pragma unroll
        for (int bs = 0; bs < 8; bs++) {
            const int mid = (lo + hi) >> 1;
            if (sb[mid] <= edge) lo = mid + 1; else hi = mid;
        }
        lut[q] = lo;                    // lo >= 1 since sb[0] = b0 <= edge
    }
    __syncthreads();

    float loss1 = 0.0f;
    unsigned int cnt = 0;
    bool sawInvalid = false;

    const int base = batch * HW + blk * PPB;
    const float4* t4 = (const float4*)(tdm + base);
    const int4*   m4 = (const int4*)(mask + base);

    #pragma unroll
    for (int it = 0; it < PPB / (4 * TH); it++) {       // 2 iterations, 8 px/thread
        const int i = it * TH + tid;
        const float4 tv = t4[i];
        const int4   mv = m4[i];
        const float gv[4] = {tv.x, tv.y, tv.z, tv.w};
        const int   mk[4] = {mv.x, mv.y, mv.z, mv.w};
        #pragma unroll
        for (int k = 0; k < 4; k++) {
            if (mk[k] != 0) {
                const float g = fmaxf(gv[k], b0);
                int q = (int)((g - b0) * lutScale);
                q = max(0, min(LUTN - 1, q));
                int s = lut[q];
                float hiv = sb[s];
                while (hiv <= g) hiv = sb[++s];          // ~0.13 extra iters avg
                loss1 += fminf(g - sb[s - 1], hiv - g);
                cnt++;
                const int gi = __float_as_int(g);        // g>0: int order==float order
                if (gi > spmax[s]) atomicMax(&spmax[s], gi);   // monotonic: race-safe
                if (gi < spmin[s]) atomicMin(&spmin[s], gi);
            } else {
                sawInvalid = true;       // invalid: loss1 += 0, handled once below
            }
        }
    }
    if (sawInvalid) sflag = 1;                           // benign race
    __syncthreads();

    if (tid == 0 && sflag) {             // one b0 segment update for all invalids
        int s = 1;                       // upper_bound(b0) = 1 (bins sorted, distinct)
        while (sb[s] <= b0) s++;
        const int bi = __float_as_int(b0);
        if (bi > spmax[s]) atomicMax(&spmax[s], bi);
        if (bi < spmin[s]) atomicMin(&spmin[s], bi);
    }

    // block reduce loss1 & count
    #pragma unroll
    for (int off = 16; off; off >>= 1) {
        loss1 += __shfl_down_sync(0xFFFFFFFFu, loss1, off);
        cnt   += __shfl_down_sync(0xFFFFFFFFu, cnt,   off);
    }
    if ((tid & 31) == 0) { wl[tid >> 5] = loss1; wc[tid >> 5] = cnt; }
    __syncthreads();

    // publish partials
    if (tid == 0) {
        float L = 0.0f; unsigned int C = 0;
        #pragma unroll
        for (int w = 0; w < TH / 32; w++) { L += wl[w]; C += wc[w]; }
        g_pl1[bid] = L; g_pcnt[bid] = C;
    }
    for (int i = tid; i < NSEG; i += TH) {
        g_pmax[bid * NSEG + i] = spmax[i];
        g_pmin[bid * NSEG + i] = spmin[i];
    }
    __threadfence();
    if (tid == 0) s_tick = atomicAdd(&g_tick_b[batch], 1u);
    __syncthreads();
    if (s_tick != BPB - 1) return;

    // ---------------- batch finalizer (one block per batch) ----------------
    __threadfence();
    if (tid == 0) g_tick_b[batch] = 0;                   // reset for next replay

    __shared__ float pref[NSEG], suf[NSEG];
    for (int i = tid; i < 2 * NSEG; i += TH) {           // merge 24 partials/segment
        const int seg = (i < NSEG) ? i : (i - NSEG);
        const int mbase = (batch * BPB) * NSEG + seg;
        if (i < NSEG) {
            int mx = -1;
            #pragma unroll 8
            for (int b = 0; b < BPB; b++) mx = max(mx, g_pmax[mbase + b * NSEG]);
            pref[seg] = (mx == -1) ? -1e30f : __int_as_float(mx);
        } else {
            int mn = INF_BITS;
            #pragma unroll 8
            for (int b = 0; b < BPB; b++) mn = min(mn, g_pmin[mbase + b * NSEG]);
            suf[seg] = (mn == INF_BITS) ? 1e30f : __int_as_float(mn);
        }
    }
    float L = 0.0f; unsigned int C = 0;
    if (tid < 32) {
        if (tid < BPB) { L = g_pl1[batch * BPB + tid]; C = g_pcnt[batch * BPB + tid]; }
        #pragma unroll
        for (int off = 16; off; off >>= 1) {
            L += __shfl_down_sync(0xFFFFFFFFu, L, off);
            C += __shfl_down_sync(0xFFFFFFFFu, C, off);
        }
    }
    __syncthreads();

    // Parallel scans: pref = inclusive prefix-max, suf = inclusive suffix-min.
    #pragma unroll
    for (int off = 1; off < NSEG; off <<= 1) {           // 8 Hillis-Steele steps
        float a = 0.0f, bmn = 0.0f;
        if (tid < NSEG) {
            a = pref[tid];
            if (tid >= off) a = fmaxf(a, pref[tid - off]);
            bmn = suf[tid];
            if (tid + off < NSEG) bmn = fminf(bmn, suf[tid + off]);
        }
        __syncthreads();
        if (tid < NSEG) { pref[tid] = a; suf[tid] = bmn; }
        __syncthreads();
    }

    float v = 0.0f;
    if (tid < DB) {
        const float bj = sb[tid];
        v = fminf(bj - pref[tid], suf[tid + 1] - bj);    // exact per-bin min dist
    }
    #pragma unroll
    for (int off = 16; off; off >>= 1) v += __shfl_down_sync(0xFFFFFFFFu, v, off);
    __shared__ float wv[TH / 32];
    if ((tid & 31) == 0) wv[tid >> 5] = v;
    if (tid == 0) { wl[0] = L; wc[0] = C; }              // stash batch L/C
    __syncthreads();

    if (tid == 0) {
        const float loss2 = wv[0] + wv[1] + wv[2] + wv[3];
        g_bsum[batch] = wl[0] + loss2;
        g_bcnt[batch] = wc[0];
        __threadfence();
        const unsigned int t2 = atomicAdd(&g_tick_g, 1u);
        if (t2 == NB - 1) {                              // global finalizer
            g_tick_g = 0;
            __threadfence();
            unsigned int tot = 0;
            #pragma unroll
            for (int b = 0; b < NB; b++) tot += g_bcnt[b];
            const float inv = 1.0f / (float)tot;
            #pragma unroll
            for (int b = 0; b < NB; b++) out[b] = g_bsum[b] * inv;
        }
    }
}

extern "C" void kernel_launch(void* const* d_in, const int* in_sizes, int n_in,
                              void* d_out, int out_size) {
    const float* bins = (const float*)d_in[0];
    const float* tdm  = (const float*)d_in[1];
    const int*   msk  = (const int*)d_in[2];
    float*       out  = (float*)d_out;

    bcl_fused<<<NB * BPB, TH>>>(bins, tdm, msk, out);
}

// round 8
// speedup vs baseline: 1.0732x; 1.0732x over previous
#include <cuda_runtime.h>

// BinsChamferLoss: n=16, d=128, h=192, w=256.  Two-kernel pipeline.
// out[b] = (loss1[b] + loss2[b]) / sum(valid_mask)   (count over ALL batches)
//   g = valid ? max(t, bins[b][0]) : bins[b][0]
//   loss1[b] = sum_pixels min_bins |g - bin|   (uniform LUT + short scan,
//                                               branchless for ALL pixels)
//   loss2[b] = sum_bins  min_pixels |g - bin|  (segment min/max + parallel scans)
//
// R8: kernel split removes threadfence/ticket/finalizer from the 384-block
// kernel's critical path (launch boundary = free global ordering). Main loop is
// branchless (R6 beat R7: divergent skip saved nothing, idle lanes cost issue
// slots anyway); atomics/count masked by predicates only.

#define NB   16
#define DB   128
#define HW   49152            // 192*256
#define BPB  24               // blocks per batch
#define PPB  (HW / BPB)       // 2048 pixels per block
#define TH   256
#define NSEG (DB + 1)         // segment s in [1,128]; slot 0 unused
#define LUTN 1024
#define INF_BITS 0x7F800000

// Per-block partials (no init required; fully overwritten every replay).
__device__ float        g_pl1 [NB * BPB];
__device__ unsigned int g_pcnt[NB * BPB];
__device__ int          g_pmax[NB * BPB * NSEG];   // float bits; -1 = empty
__device__ int          g_pmin[NB * BPB * NSEG];   // INF_BITS = empty
// Stage-2 scratch (written before read each replay; ticket resets to 0).
__device__ float        g_bsum[NB];
__device__ unsigned int g_bcnt[NB];
__device__ unsigned int g_tick_g;

__global__ __launch_bounds__(TH) void bcl_main(const float* __restrict__ bins,
                                               const float* __restrict__ tdm,
                                               const int*   __restrict__ mask) {
    const int batch = blockIdx.x / BPB;
    const int blk   = blockIdx.x % BPB;
    const int bid   = blockIdx.x;
    const int tid   = threadIdx.x;

    __shared__ float sb[NSEG];          // sorted bins + inf pad
    __shared__ int   lut[LUTN];         // lut[q] = upper_bound(edge_q) in [1,128]
    __shared__ int   spmax[NSEG];
    __shared__ int   spmin[NSEG];
    __shared__ int   sflag;             // any invalid pixel seen
    __shared__ float        wl[TH / 32];
    __shared__ unsigned int wc[TH / 32];

    if (tid < DB)   sb[tid] = bins[batch * DB + tid];
    if (tid == DB)  sb[DB]  = __int_as_float(INF_BITS);
    for (int i = tid; i < NSEG; i += TH) { spmax[i] = -1; spmin[i] = INF_BITS; }
    if (tid == 0) sflag = 0;
    __syncthreads();

    const float b0       = sb[0];
    const float lutHi    = fmaxf(10.0f, sb[DB - 1]) + 1e-3f;
    const float lutScale = (float)LUTN / (lutHi - b0);
    const float invScale = (lutHi - b0) * (1.0f / (float)LUTN);

    // lut[q] = first s with sb[s] > edge_q, edge_q = b0 + q*invScale  (s >= 1).
    for (int q = tid; q < LUTN; q += TH) {
        const float edge = b0 + (float)q * invScale;
        int lo = 0, hi = DB;
        #pragma unroll
        for (int bs = 0; bs < 8; bs++) {
            const int mid = (lo + hi) >> 1;
            if (sb[mid] <= edge) lo = mid + 1; else hi = mid;
        }
        lut[q] = lo;
    }
    __syncthreads();

    float loss1 = 0.0f;
    unsigned int cnt = 0;
    bool sawInvalid = false;

    const int base = batch * HW + blk * PPB;
    const float4* t4 = (const float4*)(tdm + base);
    const int4*   m4 = (const int4*)(mask + base);

    #pragma unroll
    for (int it = 0; it < PPB / (4 * TH); it++) {       // 2 iterations, 8 px/thread
        const int i = it * TH + tid;
        const float4 tv = t4[i];
        const int4   mv = m4[i];
        const float gv[4] = {tv.x, tv.y, tv.z, tv.w};
        const int   mk[4] = {mv.x, mv.y, mv.z, mv.w};
        #pragma unroll
        for (int k = 0; k < 4; k++) {
            const bool valid = (mk[k] != 0);
            const float g = valid ? fmaxf(gv[k], b0) : b0;   // invalid -> g=b0, dist 0
            int q = (int)((g - b0) * lutScale);
            q = max(0, min(LUTN - 1, q));
            int s = lut[q];
            float hiv = sb[s];
            while (hiv <= g) hiv = sb[++s];              // ~0.13 extra iters avg
            loss1 += fminf(g - sb[s - 1], hiv - g);      // exactly 0 when invalid
            cnt += valid ? 1u : 0u;
            sawInvalid |= !valid;
            const int gi = __float_as_int(g);            // g>0: int order==float order
            if (valid && gi > spmax[s]) atomicMax(&spmax[s], gi);  // monotonic: safe
            if (valid && gi < spmin[s]) atomicMin(&spmin[s], gi);
        }
    }
    if (sawInvalid) sflag = 1;                           // benign race
    __syncthreads();

    if (tid == 0 && sflag) {             // one b0 segment update for all invalids
        int s = 1;
        while (sb[s] <= b0) s++;
        const int bi = __float_as_int(b0);
        if (bi > spmax[s]) atomicMax(&spmax[s], bi);
        if (bi < spmin[s]) atomicMin(&spmin[s], bi);
    }

    // block reduce loss1 & count
    #pragma unroll
    for (int off = 16; off; off >>= 1) {
        loss1 += __shfl_down_sync(0xFFFFFFFFu, loss1, off);
        cnt   += __shfl_down_sync(0xFFFFFFFFu, cnt,   off);
    }
    if ((tid & 31) == 0) { wl[tid >> 5] = loss1; wc[tid >> 5] = cnt; }
    __syncthreads();

    // publish partials (plain stores; kernel boundary orders them for stage 2)
    if (tid == 0) {
        float L = 0.0f; unsigned int C = 0;
        #pragma unroll
        for (int w = 0; w < TH / 32; w++) { L += wl[w]; C += wc[w]; }
        g_pl1[bid] = L; g_pcnt[bid] = C;
    }
    for (int i = tid; i < NSEG; i += TH) {
        g_pmax[bid * NSEG + i] = spmax[i];
        g_pmin[bid * NSEG + i] = spmin[i];
    }
}

__global__ __launch_bounds__(TH) void bcl_fin(const float* __restrict__ bins,
                                              float* __restrict__ out) {
    const int batch = blockIdx.x;
    const int tid   = threadIdx.x;

    __shared__ float sb[NSEG];
    __shared__ float pref[NSEG], suf[NSEG];
    __shared__ float        wl[TH / 32];
    __shared__ unsigned int wc[TH / 32];

    if (tid < DB)  sb[tid] = bins[batch * DB + tid];
    if (tid == DB) sb[DB]  = __int_as_float(INF_BITS);

    for (int i = tid; i < 2 * NSEG; i += TH) {           // merge 24 partials/segment
        const int seg = (i < NSEG) ? i : (i - NSEG);
        const int mbase = (batch * BPB) * NSEG + seg;
        if (i < NSEG) {
            int mx = -1;
            #pragma unroll 8
            for (int b = 0; b < BPB; b++) mx = max(mx, g_pmax[mbase + b * NSEG]);
            pref[seg] = (mx == -1) ? -1e30f : __int_as_float(mx);
        } else {
            int mn = INF_BITS;
            #pragma unroll 8
            for (int b = 0; b < BPB; b++) mn = min(mn, g_pmin[mbase + b * NSEG]);
            suf[seg] = (mn == INF_BITS) ? 1e30f : __int_as_float(mn);
        }
    }
    float L = 0.0f; unsigned int C = 0;
    if (tid < 32) {
        if (tid < BPB) { L = g_pl1[batch * BPB + tid]; C = g_pcnt[batch * BPB + tid]; }
        #pragma unroll
        for (int off = 16; off; off >>= 1) {
            L += __shfl_down_sync(0xFFFFFFFFu, L, off);
            C += __shfl_down_sync(0xFFFFFFFFu, C, off);
        }
    }
    if (tid == 0) { wl[0] = L; wc[0] = C; }
    __syncthreads();

    // Parallel scans: pref = inclusive prefix-max, suf = inclusive suffix-min.
    #pragma unroll
    for (int off = 1; off < NSEG; off <<= 1) {           // 8 Hillis-Steele steps
        float a = 0.0f, bmn = 0.0f;
        if (tid < NSEG) {
            a = pref[tid];
            if (tid >= off) a = fmaxf(a, pref[tid - off]);
            bmn = suf[tid];
            if (tid + off < NSEG) bmn = fminf(bmn, suf[tid + off]);
        }
        __syncthreads();
        if (tid < NSEG) { pref[tid] = a; suf[tid] = bmn; }
        __syncthreads();
    }

    float v = 0.0f;
    if (tid < DB) {
        const float bj = sb[tid];
        v = fminf(bj - pref[tid], suf[tid + 1] - bj);    // exact per-bin min dist
    }
    #pragma unroll
    for (int off = 16; off; off >>= 1) v += __shfl_down_sync(0xFFFFFFFFu, v, off);
    __shared__ float wv[TH / 32];
    if ((tid & 31) == 0) wv[tid >> 5] = v;
    __syncthreads();

    if (tid == 0) {
        const float loss2 = wv[0] + wv[1] + wv[2] + wv[3];
        g_bsum[batch] = wl[0] + loss2;
        g_bcnt[batch] = wc[0];
        __threadfence();
        const unsigned int t2 = atomicAdd(&g_tick_g, 1u);
        if (t2 == NB - 1) {                              // last of 16 blocks
            g_tick_g = 0;
            __threadfence();
            unsigned int tot = 0;
            #pragma unroll
            for (int b = 0; b < NB; b++) tot += g_bcnt[b];
            const float inv = 1.0f / (float)tot;
            #pragma unroll
            for (int b = 0; b < NB; b++) out[b] = g_bsum[b] * inv;
        }
    }
}

extern "C" void kernel_launch(void* const* d_in, const int* in_sizes, int n_in,
                              void* d_out, int out_size) {
    const float* bins = (const float*)d_in[0];
    const float* tdm  = (const float*)d_in[1];
    const int*   msk  = (const int*)d_in[2];
    float*       out  = (float*)d_out;

    bcl_main<<<NB * BPB, TH>>>(bins, tdm, msk);
    bcl_fin<<<NB, TH>>>(bins, out);
}

// round 10
// speedup vs baseline: 1.0915x; 1.0170x over previous
#include <cuda_runtime.h>

// BinsChamferLoss: n=16, d=128, h=192, w=256.  Two-kernel pipeline.
// out[b] = (loss1[b] + loss2[b]) / sum(valid_mask)   (count over ALL batches)
//   g = valid ? max(t, bins[b][0]) : bins[b][0]
//   loss1[b] = sum_pixels min_bins |g - bin|   (uniform LUT + short scan)
//   loss2[b] = sum_bins  min_pixels |g - bin|  (segment min/max + parallel scans)
//
// R10 = R9 resubmit (R9 bench was an infra failure, no signal). Occupancy is
// GRID-limited (384 blocks x 8 warps = 21 warps/SM at TH=256). Blocks enlarged
// to 512 threads (same grid, same total per-block overhead) -> ~41 warps/SM.
// Each thread handles exactly one float4/int4 (4 pixels).

#define NB   16
#define DB   128
#define HW   49152            // 192*256
#define BPB  24               // blocks per batch
#define PPB  (HW / BPB)       // 2048 pixels per block
#define TH   512              // 4 pixels per thread, no pixel loop
#define TFIN 256
#define NSEG (DB + 1)         // segment s in [1,128]; slot 0 unused
#define LUTN 1024
#define INF_BITS 0x7F800000

// Per-block partials (no init required; fully overwritten every replay).
__device__ float        g_pl1 [NB * BPB];
__device__ unsigned int g_pcnt[NB * BPB];
__device__ int          g_pmax[NB * BPB * NSEG];   // float bits; -1 = empty
__device__ int          g_pmin[NB * BPB * NSEG];   // INF_BITS = empty
// Stage-2 scratch (written before read each replay; ticket resets to 0).
__device__ float        g_bsum[NB];
__device__ unsigned int g_bcnt[NB];
__device__ unsigned int g_tick_g;

__global__ __launch_bounds__(TH, 1) void bcl_main(const float* __restrict__ bins,
                                                  const float* __restrict__ tdm,
                                                  const int*   __restrict__ mask) {
    const int batch = blockIdx.x / BPB;
    const int blk   = blockIdx.x % BPB;
    const int bid   = blockIdx.x;
    const int tid   = threadIdx.x;

    __shared__ float sb[NSEG];          // sorted bins + inf pad
    __shared__ int   lut[LUTN];         // lut[q] = upper_bound(edge_q) in [1,128]
    __shared__ int   spmax[NSEG];
    __shared__ int   spmin[NSEG];
    __shared__ int   sflag;             // any invalid pixel seen
    __shared__ float        wl[TH / 32];
    __shared__ unsigned int wc[TH / 32];

    if (tid < DB)   sb[tid] = bins[batch * DB + tid];
    if (tid == DB)  sb[DB]  = __int_as_float(INF_BITS);
    if (tid < NSEG) { spmax[tid] = -1; spmin[tid] = INF_BITS; }
    if (tid == 0) sflag = 0;
    __syncthreads();

    const float b0       = sb[0];
    const float lutHi    = fmaxf(10.0f, sb[DB - 1]) + 1e-3f;
    const float lutScale = (float)LUTN / (lutHi - b0);
    const float invScale = (lutHi - b0) * (1.0f / (float)LUTN);

    // lut[q] = first s with sb[s] > edge_q, edge_q = b0 + q*invScale  (s >= 1).
    #pragma unroll
    for (int qq = 0; qq < LUTN / TH; qq++) {
        const int q = qq * TH + tid;
        const float edge = b0 + (float)q * invScale;
        int lo = 0, hi = DB;
        #pragma unroll
        for (int bs = 0; bs < 8; bs++) {
            const int mid = (lo + hi) >> 1;
            if (sb[mid] <= edge) lo = mid + 1; else hi = mid;
        }
        lut[q] = lo;
    }
    __syncthreads();

    float loss1 = 0.0f;
    unsigned int cnt = 0;
    bool sawInvalid = false;

    const int base = batch * HW + blk * PPB;
    const float4 tv = ((const float4*)(tdm + base))[tid];   // 4 px/thread
    const int4   mv = ((const int4*)(mask + base))[tid];
    const float gv[4] = {tv.x, tv.y, tv.z, tv.w};
    const int   mk[4] = {mv.x, mv.y, mv.z, mv.w};

    #pragma unroll
    for (int k = 0; k < 4; k++) {
        const bool valid = (mk[k] != 0);
        const float g = valid ? fmaxf(gv[k], b0) : b0;   // invalid -> g=b0, dist 0
        int q = (int)((g - b0) * lutScale);
        q = max(0, min(LUTN - 1, q));
        int s = lut[q];
        float hiv = sb[s];
        while (hiv <= g) hiv = sb[++s];                  // ~0.13 extra iters avg
        loss1 += fminf(g - sb[s - 1], hiv - g);          // exactly 0 when invalid
        cnt += valid ? 1u : 0u;
        sawInvalid |= !valid;
        const int gi = __float_as_int(g);                // g>0: int order==float order
        if (valid && gi > spmax[s]) atomicMax(&spmax[s], gi);    // monotonic: safe
        if (valid && gi < spmin[s]) atomicMin(&spmin[s], gi);
    }
    if (sawInvalid) sflag = 1;                           // benign race
    __syncthreads();

    if (tid == 0 && sflag) {             // one b0 segment update for all invalids
        int s = 1;
        while (sb[s] <= b0) s++;
        const int bi = __float_as_int(b0);
        if (bi > spmax[s]) atomicMax(&spmax[s], bi);
        if (bi < spmin[s]) atomicMin(&spmin[s], bi);
    }

    // block reduce loss1 & count
    #pragma unroll
    for (int off = 16; off; off >>= 1) {
        loss1 += __shfl_down_sync(0xFFFFFFFFu, loss1, off);
        cnt   += __shfl_down_sync(0xFFFFFFFFu, cnt,   off);
    }
    if ((tid & 31) == 0) { wl[tid >> 5] = loss1; wc[tid >> 5] = cnt; }
    __syncthreads();

    // publish partials (plain stores; kernel boundary orders them for stage 2)
    if (tid == 0) {
        float L = 0.0f; unsigned int C = 0;
        #pragma unroll
        for (int w = 0; w < TH / 32; w++) { L += wl[w]; C += wc[w]; }
        g_pl1[bid] = L; g_pcnt[bid] = C;
    }
    if (tid < NSEG) {
        g_pmax[bid * NSEG + tid] = spmax[tid];
        g_pmin[bid * NSEG + tid] = spmin[tid];
    }
}

__global__ __launch_bounds__(TFIN) void bcl_fin(const float* __restrict__ bins,
                                                float* __restrict__ out) {
    const int batch = blockIdx.x;
    const int tid   = threadIdx.x;

    __shared__ float sb[NSEG];
    __shared__ float pref[NSEG], suf[NSEG];
    __shared__ float        wl[TFIN / 32];
    __shared__ unsigned int wc[TFIN / 32];

    if (tid < DB)  sb[tid] = bins[batch * DB + tid];
    if (tid == DB) sb[DB]  = __int_as_float(INF_BITS);

    for (int i = tid; i < 2 * NSEG; i += TFIN) {         // merge 24 partials/segment
        const int seg = (i < NSEG) ? i : (i - NSEG);
        const int mbase = (batch * BPB) * NSEG + seg;
        if (i < NSEG) {
            int mx = -1;
            #pragma unroll 8
            for (int b = 0; b < BPB; b++) mx = max(mx, g_pmax[mbase + b * NSEG]);
            pref[seg] = (mx == -1) ? -1e30f : __int_as_float(mx);
        } else {
            int mn = INF_BITS;
            #pragma unroll 8
            for (int b = 0; b < BPB; b++) mn = min(mn, g_pmin[mbase + b * NSEG]);
            suf[seg] = (mn == INF_BITS) ? 1e30f : __int_as_float(mn);
        }
    }
    float L = 0.0f; unsigned int C = 0;
    if (tid < 32) {
        if (tid < BPB) { L = g_pl1[batch * BPB + tid]; C = g_pcnt[batch * BPB + tid]; }
        #pragma unroll
        for (int off = 16; off; off >>= 1) {
            L += __shfl_down_sync(0xFFFFFFFFu, L, off);
            C += __shfl_down_sync(0xFFFFFFFFu, C, off);
        }
    }
    if (tid == 0) { wl[0] = L; wc[0] = C; }
    __syncthreads();

    // Parallel scans: pref = inclusive prefix-max, suf = inclusive suffix-min.
    #pragma unroll
    for (int off = 1; off < NSEG; off <<= 1) {           // 8 Hillis-Steele steps
        float a = 0.0f, bmn = 0.0f;
        if (tid < NSEG) {
            a = pref[tid];
            if (tid >= off) a = fmaxf(a, pref[tid - off]);
            bmn = suf[tid];
            if (tid + off < NSEG) bmn = fminf(bmn, suf[tid + off]);
        }
        __syncthreads();
        if (tid < NSEG) { pref[tid] = a; suf[tid] = bmn; }
        __syncthreads();
    }

    float v = 0.0f;
    if (tid < DB) {
        const float bj = sb[tid];
        v = fminf(bj - pref[tid], suf[tid + 1] - bj);    // exact per-bin min dist
    }
    #pragma unroll
    for (int off = 16; off; off >>= 1) v += __shfl_down_sync(0xFFFFFFFFu, v, off);
    __shared__ float wv[TFIN / 32];
    if ((tid & 31) == 0) wv[tid >> 5] = v;
    __syncthreads();

    if (tid == 0) {
        const float loss2 = wv[0] + wv[1] + wv[2] + wv[3];
        g_bsum[batch] = wl[0] + loss2;
        g_bcnt[batch] = wc[0];
        __threadfence();
        const unsigned int t2 = atomicAdd(&g_tick_g, 1u);
        if (t2 == NB - 1) {                              // last of 16 blocks
            g_tick_g = 0;
            __threadfence();
            unsigned int tot = 0;
            #pragma unroll
            for (int b = 0; b < NB; b++) tot += g_bcnt[b];
            const float inv = 1.0f / (float)tot;
            #pragma unroll
            for (int b = 0; b < NB; b++) out[b] = g_bsum[b] * inv;
        }
    }
}

extern "C" void kernel_launch(void* const* d_in, const int* in_sizes, int n_in,
                              void* d_out, int out_size) {
    const float* bins = (const float*)d_in[0];
    const float* tdm  = (const float*)d_in[1];
    const int*   msk  = (const int*)d_in[2];
    float*       out  = (float*)d_out;

    bcl_main<<<NB * BPB, TH>>>(bins, tdm, msk);
    bcl_fin<<<NB, TFIN>>>(bins, out);
}

// round 11
// speedup vs baseline: 1.1350x; 1.0398x over previous
#include <cuda_runtime.h>

// BinsChamferLoss: n=16, d=128, h=192, w=256.  Two-kernel pipeline.
// out[b] = (loss1[b] + loss2[b]) / sum(valid_mask)   (count over ALL batches)
//   g = valid ? max(t, bins[b][0]) : bins[b][0]
//   loss1[b] = sum_pixels min_bins |g - bin|   (uniform LUT + short scan)
//   loss2[b] = sum_bins  min_pixels |g - bin|  (per-batch segment extrema via
//                                               REDG + parallel scans)
//
// R11: fin's merge was 6192 strided 4B loads/block (every load its own sector)
// — the hidden tail. Cross-block merge now happens in main via fire-and-forget
// global atomicMax into per-batch tables; "empty"=0 encoding (min stored as
// 0x7FFFFFFF-bits) makes zero-init natural, and fin resets entries to 0 after
// reading so graph replays stay deterministic.

#define NB   16
#define DB   128
#define HW   49152            // 192*256
#define BPB  24               // blocks per batch
#define PPB  (HW / BPB)       // 2048 pixels per block
#define TH   512              // 4 pixels per thread, no pixel loop
#define TFIN 256
#define NSEG (DB + 1)         // segment s in [1,128]; slot 0 unused
#define LUTN 1024
#define INF_BITS 0x7F800000

// Per-batch segment extrema; 0 = empty (zero .bss start, reset by fin).
__device__ int          g_bmax[NB * NSEG];   // float bits of segment max
__device__ int          g_bmin[NB * NSEG];   // 0x7FFFFFFF - float bits of min
// Per-block sums (plain stores, fully overwritten every replay).
__device__ float        g_pl1 [NB * BPB];
__device__ unsigned int g_pcnt[NB * BPB];
// Stage-2 scratch (written before read each replay; ticket resets to 0).
__device__ float        g_bsum[NB];
__device__ unsigned int g_bcnt[NB];
__device__ unsigned int g_tick_g;

__global__ __launch_bounds__(TH, 1) void bcl_main(const float* __restrict__ bins,
                                                  const float* __restrict__ tdm,
                                                  const int*   __restrict__ mask) {
    const int batch = blockIdx.x / BPB;
    const int blk   = blockIdx.x % BPB;
    const int bid   = blockIdx.x;
    const int tid   = threadIdx.x;

    __shared__ float sb[NSEG];          // sorted bins + inf pad
    __shared__ int   lut[LUTN];         // lut[q] = upper_bound(edge_q) in [1,128]
    __shared__ int   spmax[NSEG];
    __shared__ int   spmin[NSEG];
    __shared__ int   sflag;             // any invalid pixel seen
    __shared__ float        wl[TH / 32];
    __shared__ unsigned int wc[TH / 32];

    if (tid < DB)   sb[tid] = bins[batch * DB + tid];
    if (tid == DB)  sb[DB]  = __int_as_float(INF_BITS);
    if (tid < NSEG) { spmax[tid] = -1; spmin[tid] = INF_BITS; }
    if (tid == 0) sflag = 0;
    __syncthreads();

    const float b0       = sb[0];
    const float lutHi    = fmaxf(10.0f, sb[DB - 1]) + 1e-3f;
    const float lutScale = (float)LUTN / (lutHi - b0);
    const float invScale = (lutHi - b0) * (1.0f / (float)LUTN);

    // lut[q] = first s with sb[s] > edge_q, edge_q = b0 + q*invScale  (s >= 1).
    #pragma unroll
    for (int qq = 0; qq < LUTN / TH; qq++) {
        const int q = qq * TH + tid;
        const float edge = b0 + (float)q * invScale;
        int lo = 0, hi = DB;
        #pragma unroll
        for (int bs = 0; bs < 8; bs++) {
            const int mid = (lo + hi) >> 1;
            if (sb[mid] <= edge) lo = mid + 1; else hi = mid;
        }
        lut[q] = lo;
    }
    __syncthreads();

    float loss1 = 0.0f;
    unsigned int cnt = 0;
    bool sawInvalid = false;

    const int base = batch * HW + blk * PPB;
    const float4 tv = ((const float4*)(tdm + base))[tid];   // 4 px/thread
    const int4   mv = ((const int4*)(mask + base))[tid];
    const float gv[4] = {tv.x, tv.y, tv.z, tv.w};
    const int   mk[4] = {mv.x, mv.y, mv.z, mv.w};

    #pragma unroll
    for (int k = 0; k < 4; k++) {
        const bool valid = (mk[k] != 0);
        const float g = valid ? fmaxf(gv[k], b0) : b0;   // invalid -> g=b0, dist 0
        int q = (int)((g - b0) * lutScale);
        q = max(0, min(LUTN - 1, q));
        int s = lut[q];
        float hiv = sb[s];
        while (hiv <= g) hiv = sb[++s];                  // ~0.13 extra iters avg
        loss1 += fminf(g - sb[s - 1], hiv - g);          // exactly 0 when invalid
        cnt += valid ? 1u : 0u;
        sawInvalid |= !valid;
        const int gi = __float_as_int(g);                // g>0: int order==float order
        if (valid && gi > spmax[s]) atomicMax(&spmax[s], gi);    // monotonic: safe
        if (valid && gi < spmin[s]) atomicMin(&spmin[s], gi);
    }
    if (sawInvalid) sflag = 1;                           // benign race
    __syncthreads();

    if (tid == 0 && sflag) {             // one b0 segment update for all invalids
        int s = 1;
        while (sb[s] <= b0) s++;
        const int bi = __float_as_int(b0);
        if (bi > spmax[s]) atomicMax(&spmax[s], bi);
        if (bi < spmin[s]) atomicMin(&spmin[s], bi);
    }

    // block reduce loss1 & count
    #pragma unroll
    for (int off = 16; off; off >>= 1) {
        loss1 += __shfl_down_sync(0xFFFFFFFFu, loss1, off);
        cnt   += __shfl_down_sync(0xFFFFFFFFu, cnt,   off);
    }
    if ((tid & 31) == 0) { wl[tid >> 5] = loss1; wc[tid >> 5] = cnt; }
    __syncthreads();

    // publish: sums as plain stores; segment extrema as fire-and-forget REDG
    // into per-batch tables (0 = empty; min flipped so atomicMax does min).
    if (tid == 0) {
        float L = 0.0f; unsigned int C = 0;
        #pragma unroll
        for (int w = 0; w < TH / 32; w++) { L += wl[w]; C += wc[w]; }
        g_pl1[bid] = L; g_pcnt[bid] = C;
    }
    if (tid < NSEG) {
        const int mx = spmax[tid];
        if (mx != -1)       atomicMax(&g_bmax[batch * NSEG + tid], mx);
        const int mn = spmin[tid];
        if (mn != INF_BITS) atomicMax(&g_bmin[batch * NSEG + tid], 0x7FFFFFFF - mn);
    }
}

__global__ __launch_bounds__(TFIN) void bcl_fin(const float* __restrict__ bins,
                                                float* __restrict__ out) {
    const int batch = blockIdx.x;
    const int tid   = threadIdx.x;

    __shared__ float sb[NSEG];
    __shared__ float pref[NSEG], suf[NSEG];
    __shared__ float        wl[TFIN / 32];
    __shared__ unsigned int wc[TFIN / 32];

    if (tid < DB)  sb[tid] = bins[batch * DB + tid];
    if (tid == DB) sb[DB]  = __int_as_float(INF_BITS);

    if (tid < NSEG) {                    // coalesced per-batch reads + reset to 0
        const int idx = batch * NSEG + tid;
        const int mx  = g_bmax[idx];
        const int mn2 = g_bmin[idx];
        g_bmax[idx] = 0;                 // clean state for next graph replay
        g_bmin[idx] = 0;
        pref[tid] = (mx  == 0) ? -1e30f : __int_as_float(mx);
        suf [tid] = (mn2 == 0) ?  1e30f : __int_as_float(0x7FFFFFFF - mn2);
    }
    float L = 0.0f; unsigned int C = 0;
    if (tid < 32) {
        if (tid < BPB) { L = g_pl1[batch * BPB + tid]; C = g_pcnt[batch * BPB + tid]; }
        #pragma unroll
        for (int off = 16; off; off >>= 1) {
            L += __shfl_down_sync(0xFFFFFFFFu, L, off);
            C += __shfl_down_sync(0xFFFFFFFFu, C, off);
        }
    }
    if (tid == 0) { wl[0] = L; wc[0] = C; }
    __syncthreads();

    // Parallel scans: pref = inclusive prefix-max, suf = inclusive suffix-min.
    #pragma unroll
    for (int off = 1; off < NSEG; off <<= 1) {           // 8 Hillis-Steele steps
        float a = 0.0f, bmn = 0.0f;
        if (tid < NSEG) {
            a = pref[tid];
            if (tid >= off) a = fmaxf(a, pref[tid - off]);
            bmn = suf[tid];
            if (tid + off < NSEG) bmn = fminf(bmn, suf[tid + off]);
        }
        __syncthreads();
        if (tid < NSEG) { pref[tid] = a; suf[tid] = bmn; }
        __syncthreads();
    }

    float v = 0.0f;
    if (tid < DB) {
        const float bj = sb[tid];
        v = fminf(bj - pref[tid], suf[tid + 1] - bj);    // exact per-bin min dist
    }
    #pragma unroll
    for (int off = 16; off; off >>= 1) v += __shfl_down_sync(0xFFFFFFFFu, v, off);
    __shared__ float wv[TFIN / 32];
    if ((tid & 31) == 0) wv[tid >> 5] = v;
    __syncthreads();

    if (tid == 0) {
        const float loss2 = wv[0] + wv[1] + wv[2] + wv[3];
        g_bsum[batch] = wl[0] + loss2;
        g_bcnt[batch] = wc[0];
        __threadfence();
        const unsigned int t2 = atomicAdd(&g_tick_g, 1u);
        if (t2 == NB - 1) {                              // last of 16 blocks
            g_tick_g = 0;
            __threadfence();
            unsigned int tot = 0;
            #pragma unroll
            for (int b = 0; b < NB; b++) tot += g_bcnt[b];
            const float inv = 1.0f / (float)tot;
            #pragma unroll
            for (int b = 0; b < NB; b++) out[b] = g_bsum[b] * inv;
        }
    }
}

extern "C" void kernel_launch(void* const* d_in, const int* in_sizes, int n_in,
                              void* d_out, int out_size) {
    const float* bins = (const float*)d_in[0];
    const float* tdm  = (const float*)d_in[1];
    const int*   msk  = (const int*)d_in[2];
    float*       out  = (float*)d_out;

    bcl_main<<<NB * BPB, TH>>>(bins, tdm, msk);
    bcl_fin<<<NB, TFIN>>>(bins, out);
}